// round 11
// baseline (speedup 1.0000x reference)
#include <cuda_runtime.h>

#define CENTER_X 0.5f
#define NPTS    512
#define NBLOCKS 256   // one block per batch
#define TPB     256   // 8 warps; each thread handles exactly 2 points
#define FPSCALE 1048576.0f       // 2^20 lane-partial fixed-point scale
#define FPINV   (1.0f / 1048576.0f)

// Single packed accumulator:
//   bits [0:9)   arrival count (256 blocks)
//   bits [9:32)  exact integer pair count (sum over batches)
//   bits [32:64) fixed-point loss sum, scale 2^11
// Winner decodes the final value straight from its atomicAdd return -> no
// fences, no second accumulator, order-independent (bitwise deterministic).
// Reset to 0 by the winner each launch -> identical state every graph replay.
__device__ unsigned long long g_acc = 0ull;

__global__ __launch_bounds__(TPB) void sym_fused(const float4* __restrict__ kp4,
                                                 const int2*   __restrict__ cls2,
                                                 float*        __restrict__ out) {
    const int lane = threadIdx.x & 31;
    const int warp = threadIdx.x >> 5;
    const int idx  = blockIdx.x * (NPTS / 2) + threadIdx.x;  // one pair per thread

    const float4 p = kp4[idx];
    const int2   c = cls2[idx];

    const float ua = p.x - CENTER_X, ya = p.y;
    const float ub = p.z - CENTER_X, yb = p.w;
    const float ua2 = ua * ua, ya2 = ya * ya;
    const float ub2 = ub * ub, yb2 = yb * yb;

    // Per symmetric class k in {0,1,2}: {m(int), su, su2, sy, sy2}
    float su[3], s2[3], sy[3], q2[3];
    int   mi[3];
#pragma unroll
    for (int k = 0; k < 3; k++) {
        const bool  ia = (c.x == k), ib = (c.y == k);
        const float fa = ia ? 1.f : 0.f;
        const float fb = ib ? 1.f : 0.f;
        mi[k] = (int)ia + (int)ib;
        su[k] = fmaf(fa, ua,  fb * ub);
        s2[k] = fmaf(fa, ua2, fb * ub2);
        sy[k] = fmaf(fa, ya,  fb * yb);
        q2[k] = fmaf(fa, ya2, fb * yb2);
    }

    // Warp reduction via HW REDUX.SUM on 2^-20 fixed point.
    // |lane partial| <= 2 -> |int| <= 2^21, warp sum <= 2^26: no overflow;
    // the integer block combine below is exact.
    __shared__ int s[8][16];   // [warp][12 stats + 3 counts + pad]
    int r[16];
#pragma unroll
    for (int k = 0; k < 3; k++) {
        r[k * 4 + 0] = __reduce_add_sync(0xffffffffu, __float2int_rn(su[k] * FPSCALE));
        r[k * 4 + 1] = __reduce_add_sync(0xffffffffu, __float2int_rn(s2[k] * FPSCALE));
        r[k * 4 + 2] = __reduce_add_sync(0xffffffffu, __float2int_rn(sy[k] * FPSCALE));
        r[k * 4 + 3] = __reduce_add_sync(0xffffffffu, __float2int_rn(q2[k] * FPSCALE));
        r[12 + k]    = (int)__reduce_add_sync(0xffffffffu, (unsigned)mi[k]);
    }
    r[15] = 0;
    if (lane == 0) {
        *(int4*)&s[warp][0]  = *(int4*)&r[0];
        *(int4*)&s[warp][4]  = *(int4*)&r[4];
        *(int4*)&s[warp][8]  = *(int4*)&r[8];
        *(int4*)&s[warp][12] = *(int4*)&r[12];
    }
    __syncthreads();

    if (threadIdx.x == 0) {
        // Exact integer combine of the 8 warp rows (vectorized LDS.128).
        int t[16] = {0};
#pragma unroll
        for (int w = 0; w < 8; w++) {
#pragma unroll
            for (int q = 0; q < 4; q++) {
                const int4 v = *(int4*)&s[w][q * 4];
                t[q * 4 + 0] += v.x; t[q * 4 + 1] += v.y;
                t[q * 4 + 2] += v.z; t[q * 4 + 3] += v.w;
            }
        }

        float    tot = 0.f;
        unsigned cnt = 0u;
#pragma unroll
        for (int k = 0; k < 3; k++) {
            const unsigned mk  = (unsigned)t[12 + k];
            const float    fm  = (float)mk;
            const float    fsu = (float)t[k * 4 + 0] * FPINV;
            const float    fs2 = (float)t[k * 4 + 1] * FPINV;
            const float    fsy = (float)t[k * 4 + 2] * FPINV;
            const float    fq2 = (float)t[k * 4 + 3] * FPINV;
            // sum_{i<j}(u_i+u_j)^2 = (m-2)*su2 + su^2
            // sum_{i<j}(y_i-y_j)^2 = m*sy2 - sy^2
            tot += (fm - 2.f) * fs2 + fsu * fsu + fm * fq2 - fsy * fsy;
            cnt += (mk * (mk - 1u)) >> 1;   // exact integer pair count
        }
        // True value is a sum of squares (>= 0); clamp rounding noise so the
        // fixed-point field can never borrow into the count field.
        tot = fmaxf(tot, 0.f);

        const unsigned long long tf  = (unsigned long long)(tot * 2048.f + 0.5f);
        const unsigned long long pkt = (tf << 32) | ((unsigned long long)cnt << 9) | 1ull;
        const unsigned long long old = atomicAdd(&g_acc, pkt);

        if ((old & 0x1FFull) == (unsigned long long)(NBLOCKS - 1)) {
            // Last arriver: the RMW return already holds the exact global
            // count and the full fixed-point loss sum. No fences needed.
            const unsigned long long fin  = old + pkt;
            const float fcnt = (float)((unsigned)(fin >> 9) & 0x7FFFFFu);
            const float ftot = (float)(unsigned)(fin >> 32) * (1.0f / 2048.0f);
            out[0] = __fdividef(ftot, fmaxf(fcnt, 1.0f));
            g_acc = 0ull;   // reset for next replay (published at kernel boundary)
        }
    }
}

extern "C" void kernel_launch(void* const* d_in, const int* in_sizes, int n_in,
                              void* d_out, int out_size) {
    const float4* kp  = (const float4*)d_in[0];  // [256, 512, 2] f32 -> float4 = 2 points
    const int2*   cls = (const int2*)d_in[1];    // [256, 512] i32 -> int2 = 2 classes
    float*        out = (float*)d_out;           // scalar f32

    sym_fused<<<NBLOCKS, TPB>>>(kp, cls, out);
}

// round 13
// speedup vs baseline: 1.1082x; 1.1082x over previous
#include <cuda_runtime.h>

#define CENTER_X 0.5f
#define NPTS    512
#define NBLOCKS 256   // one block per batch
#define TPB     256   // 8 warps; each thread handles exactly 2 points
#define FPSCALE 1048576.0f       // 2^20 lane-partial fixed-point scale
#define FPINV   (1.0f / 1048576.0f)

// Single packed accumulator:
//   bits [0:9)   arrival count (256 blocks)
//   bits [9:32)  exact integer pair count (sum over batches)
//   bits [32:64) fixed-point loss sum, scale 2^11
// Winner decodes the final value straight from its atomicAdd return -> no
// fences, no second accumulator, order-independent (bitwise deterministic).
// Reset to 0 by the winner each launch -> identical state every graph replay.
__device__ unsigned long long g_acc = 0ull;

__global__ __launch_bounds__(TPB) void sym_fused(const float4* __restrict__ kp4,
                                                 const int2*   __restrict__ cls2,
                                                 float*        __restrict__ out) {
    const int lane = threadIdx.x & 31;
    const int warp = threadIdx.x >> 5;
    const int idx  = blockIdx.x * (NPTS / 2) + threadIdx.x;  // one pair per thread

    const float4 p = kp4[idx];
    const int2   c = cls2[idx];

    const float ua = p.x - CENTER_X, ya = p.y;
    const float ub = p.z - CENTER_X, yb = p.w;
    const float ua2 = ua * ua, ya2 = ya * ya;
    const float ub2 = ub * ub, yb2 = yb * yb;

    // Per symmetric class k in {0,1,2}: {m(int), su, su2, sy, sy2}
    float su[3], s2[3], sy[3], q2[3];
    int   mi[3];
#pragma unroll
    for (int k = 0; k < 3; k++) {
        const bool  ia = (c.x == k), ib = (c.y == k);
        const float fa = ia ? 1.f : 0.f;
        const float fb = ib ? 1.f : 0.f;
        mi[k] = (int)ia + (int)ib;
        su[k] = fmaf(fa, ua,  fb * ub);
        s2[k] = fmaf(fa, ua2, fb * ub2);
        sy[k] = fmaf(fa, ya,  fb * yb);
        q2[k] = fmaf(fa, ya2, fb * yb2);
    }

    // Warp reduction via HW REDUX.SUM on 2^-20 fixed point.
    // |lane partial| <= 2 -> |int| <= 2^21, warp sum <= 2^26: no overflow;
    // the integer combine below is exact.
    // Transposed layout: s[stat][warp] so the block combine is lane-parallel.
    __shared__ int s[15][8];
    int r[15];
#pragma unroll
    for (int k = 0; k < 3; k++) {
        r[k * 4 + 0] = __reduce_add_sync(0xffffffffu, __float2int_rn(su[k] * FPSCALE));
        r[k * 4 + 1] = __reduce_add_sync(0xffffffffu, __float2int_rn(s2[k] * FPSCALE));
        r[k * 4 + 2] = __reduce_add_sync(0xffffffffu, __float2int_rn(sy[k] * FPSCALE));
        r[k * 4 + 3] = __reduce_add_sync(0xffffffffu, __float2int_rn(q2[k] * FPSCALE));
        r[12 + k]    = (int)__reduce_add_sync(0xffffffffu, (unsigned)mi[k]);
    }
    if (lane == 0) {
#pragma unroll
        for (int j = 0; j < 15; j++) s[j][warp] = r[j];
    }
    __syncthreads();

    if (warp == 0) {
        // Lane j (<15) exactly sums stat j across the 8 warps (2x LDS.128).
        int sum = 0;
        if (lane < 15) {
            const int4 a = *(const int4*)&s[lane][0];
            const int4 b = *(const int4*)&s[lane][4];
            sum = a.x + a.y + a.z + a.w + b.x + b.y + b.z + b.w;
        }

        // Lanes 0-2 each gather their class's 5 stats and compute the
        // closed form in parallel (3x on the FFMA chain).
        const int k    = lane;
        const int fsu_i = __shfl_sync(0xffffffffu, sum, (4 * k + 0) & 31);
        const int fs2_i = __shfl_sync(0xffffffffu, sum, (4 * k + 1) & 31);
        const int fsy_i = __shfl_sync(0xffffffffu, sum, (4 * k + 2) & 31);
        const int fq2_i = __shfl_sync(0xffffffffu, sum, (4 * k + 3) & 31);
        const int m_i   = __shfl_sync(0xffffffffu, sum, (12 + k) & 31);

        float    tot = 0.f;
        unsigned cnt = 0u;
        if (k < 3) {
            const unsigned mk  = (unsigned)m_i;
            const float    fm  = (float)mk;
            const float    fsu = (float)fsu_i * FPINV;
            const float    fs2 = (float)fs2_i * FPINV;
            const float    fsy = (float)fsy_i * FPINV;
            const float    fq2 = (float)fq2_i * FPINV;
            // sum_{i<j}(u_i+u_j)^2 = (m-2)*su2 + su^2
            // sum_{i<j}(y_i-y_j)^2 = m*sy2 - sy^2
            tot = (fm - 2.f) * fs2 + fsu * fsu + fm * fq2 - fsy * fsy;
            cnt = (mk * (mk - 1u)) >> 1;   // exact integer pair count
        }
        // Merge lanes 0..3 (lane 3 contributes zeros) into lane 0.
        tot += __shfl_xor_sync(0xffffffffu, tot, 1);
        tot += __shfl_xor_sync(0xffffffffu, tot, 2);
        cnt += __shfl_xor_sync(0xffffffffu, cnt, 1);
        cnt += __shfl_xor_sync(0xffffffffu, cnt, 2);

        if (lane == 0) {
            // True value is a sum of squares (>= 0); clamp rounding noise so
            // the fixed-point field can never borrow into the count field.
            tot = fmaxf(tot, 0.f);

            const unsigned long long tf  = (unsigned long long)(tot * 2048.f + 0.5f);
            const unsigned long long pkt =
                (tf << 32) | ((unsigned long long)cnt << 9) | 1ull;
            const unsigned long long old = atomicAdd(&g_acc, pkt);

            if ((old & 0x1FFull) == (unsigned long long)(NBLOCKS - 1)) {
                // Last arriver: the RMW return already holds the exact global
                // count and the full fixed-point loss sum. No fences needed.
                const unsigned long long fin  = old + pkt;
                const float fcnt = (float)((unsigned)(fin >> 9) & 0x7FFFFFu);
                const float ftot = (float)(unsigned)(fin >> 32) * (1.0f / 2048.0f);
                out[0] = __fdividef(ftot, fmaxf(fcnt, 1.0f));
                g_acc = 0ull;   // reset for next replay
            }
        }
    }
}

extern "C" void kernel_launch(void* const* d_in, const int* in_sizes, int n_in,
                              void* d_out, int out_size) {
    const float4* kp  = (const float4*)d_in[0];  // [256, 512, 2] f32 -> float4 = 2 points
    const int2*   cls = (const int2*)d_in[1];    // [256, 512] i32 -> int2 = 2 classes
    float*        out = (float*)d_out;           // scalar f32

    sym_fused<<<NBLOCKS, TPB>>>(kp, cls, out);
}